// round 12
// baseline (speedup 1.0000x reference)
#include <cuda_runtime.h>
#include <cuda_bf16.h>
#include <cstdint>

// Problem constants
static constexpr int BB = 16;
static constexpr int NN = 1024;
static constexpr int MM = 1024;
static constexpr int DD = 768;
static constexpr int D2 = 2 * DD;

static constexpr int PNL = 16384;     // one panel: 128 rows x 128 bytes
static constexpr int KT_MAX = 6;      // max compacted key tiles
static constexpr int CKEYS = KT_MAX * 128;   // 768 compacted key slots
static constexpr int G1T = 8 * KT_MAX * BB;  // 768 gemm1 tiles (== gemm2 tiles)
static constexpr int NWORKERS = 296;  // 2 CTAs/SM x 148 SMs (persistent)

// Staging buffers (device globals; allocation is forbidden)
__device__ __align__(16) __nv_bfloat16 g_Qb [(size_t)BB * NN * DD];
__device__ __align__(16) __nv_bfloat16 g_Mb [(size_t)BB * CKEYS * DD];
__device__ __align__(16) __nv_bfloat16 g_P  [(size_t)BB * NN * CKEYS];
__device__ float g_den[BB * NN];
__device__ int   g_idx[BB * CKEYS];
__device__ int   g_cnt[BB];
__device__ unsigned g_done[BB * 8];
__device__ unsigned g_ctr[2];

__device__ __forceinline__ uint32_t smem_u32(const void* p) {
    return (uint32_t)__cvta_generic_to_shared(p);
}
__device__ __forceinline__ uint32_t packbf2(float lo, float hi) {
    uint32_t r;
    asm("cvt.rn.bf16x2.f32 %0, %1, %2;" : "=r"(r) : "f"(hi), "f"(lo));
    return r;
}
__device__ __forceinline__ void mbar_init(uint32_t mb, uint32_t cnt) {
    asm volatile("mbarrier.init.shared.b64 [%0], %1;" :: "r"(mb), "r"(cnt) : "memory");
}
__device__ __forceinline__ void mbar_arrive(uint32_t mb) {
    asm volatile("mbarrier.arrive.shared.b64 _, [%0];" :: "r"(mb) : "memory");
}
__device__ __forceinline__ void mbar_expect_tx(uint32_t mb, uint32_t bytes) {
    asm volatile("mbarrier.arrive.expect_tx.shared.b64 _, [%0], %1;"
                 :: "r"(mb), "r"(bytes) : "memory");
}
__device__ __forceinline__ void bulk_g2s(uint32_t dst, const void* src,
                                         uint32_t bytes, uint32_t mb) {
    asm volatile("cp.async.bulk.shared::cta.global.mbarrier::complete_tx::bytes "
                 "[%0], [%1], %2, [%3];"
                 :: "r"(dst), "l"(src), "r"(bytes), "r"(mb) : "memory");
}
__device__ __forceinline__ void mbar_wait(uint32_t mb, uint32_t parity) {
    asm volatile(
        "{\n\t"
        ".reg .pred P1;\n\t"
        "LAB_WAIT_%=:\n\t"
        "mbarrier.try_wait.parity.acquire.cta.shared::cta.b64 P1, [%0], %1, 0x989680;\n\t"
        "@P1 bra LAB_DONE_%=;\n\t"
        "bra LAB_WAIT_%=;\n\t"
        "LAB_DONE_%=:\n\t"
        "}" :: "r"(mb), "r"(parity) : "memory");
}

// ---------------------------------------------------------------------------
// Compaction: per batch, gather indices of unmasked keys. Zero g_done/g_ctr.
// ---------------------------------------------------------------------------
__global__ void compact_kernel(const int* __restrict__ mask)
{
    const int b   = blockIdx.x;
    const int tid = threadIdx.x;   // 1024 threads
    __shared__ int wbase[33];

    if (tid < 8) g_done[b * 8 + tid] = 0u;
    if (b == 0 && tid < 2) g_ctr[tid] = 0u;

    const int v = (mask[b * MM + tid] != 0) ? 1 : 0;
    const uint32_t bal = __ballot_sync(0xffffffffu, v);
    const int lane = tid & 31, w = tid >> 5;
    if (lane == 0) wbase[w + 1] = __popc(bal);
    __syncthreads();
    if (tid == 0) {
        wbase[0] = 0;
        for (int i = 1; i <= 32; ++i) wbase[i] += wbase[i - 1];
    }
    __syncthreads();
    const int cnt = wbase[32];
    if (v) {
        const int pos = wbase[w] + __popc(bal & ((1u << lane) - 1u));
        if (pos < CKEYS) g_idx[b * CKEYS + pos] = tid;
    }
    if (tid < CKEYS - cnt) g_idx[b * CKEYS + cnt + tid] = -1;
    if (tid == 0) g_cnt[b] = (cnt < CKEYS) ? cnt : CKEYS;
}

// ---------------------------------------------------------------------------
// Prep: Qb staging, compacted Mb staging (pad rows zero), out[:768] = input.
// ---------------------------------------------------------------------------
__global__ void prep_kernel(const float* __restrict__ input,
                            const float* __restrict__ memory,
                            const float* __restrict__ dot_scale,
                            float* __restrict__ out)
{
    const int64_t stride = (int64_t)gridDim.x * blockDim.x;
    const int64_t gtid   = (int64_t)blockIdx.x * blockDim.x + threadIdx.x;
    char* qb = reinterpret_cast<char*>(g_Qb);
    char* mb = reinterpret_cast<char*>(g_Mb);

    if (gtid < BB * NN) g_den[gtid] = 0.f;

    const int64_t total_q = (int64_t)BB * NN * DD / 8;
    for (int64_t i = gtid; i < total_q; i += stride) {
        const int64_t e = i * 8;
        const int d = (int)(e % DD);
        const int64_t row = e / DD;          // b*NN + n
        const int b = (int)(row >> 10);
        const int n = (int)(row & 1023);
        float4 v0 = *reinterpret_cast<const float4*>(input + e);
        float4 v1 = *reinterpret_cast<const float4*>(input + e + 4);
        float4 s0 = *reinterpret_cast<const float4*>(dot_scale + d);
        float4 s1 = *reinterpret_cast<const float4*>(dot_scale + d + 4);
        uint4 q;
        q.x = packbf2(v0.x * s0.x, v0.y * s0.y);
        q.y = packbf2(v0.z * s0.z, v0.w * s0.w);
        q.z = packbf2(v1.x * s1.x, v1.y * s1.y);
        q.w = packbf2(v1.z * s1.z, v1.w * s1.w);
        const int64_t off = (((int64_t)(b * 8 + (n >> 7)) * 12 + (d >> 6)) * 128
                             + (n & 127)) * 128
                          + (((d & 63) * 2) ^ ((n & 7) << 4));
        *reinterpret_cast<uint4*>(qb + off) = q;
        *reinterpret_cast<float4*>(out + row * D2 + d)     = v0;
        *reinterpret_cast<float4*>(out + row * D2 + d + 4) = v1;
    }

    const int64_t total_m = (int64_t)BB * CKEYS * DD / 8;
    for (int64_t i = gtid; i < total_m; i += stride) {
        const int64_t e = i * 8;
        const int d = (int)(e % DD);
        const int64_t row = e / DD;          // b*CKEYS + j
        const int b = (int)(row / CKEYS);
        const int j = (int)(row - (int64_t)b * CKEYS);
        const int src = g_idx[b * CKEYS + j];
        uint4 q = make_uint4(0u, 0u, 0u, 0u);
        if (src >= 0) {
            const float* mrow = memory + ((int64_t)(b * MM + src)) * DD + d;
            float4 v0 = *reinterpret_cast<const float4*>(mrow);
            float4 v1 = *reinterpret_cast<const float4*>(mrow + 4);
            q.x = packbf2(v0.x, v0.y);
            q.y = packbf2(v0.z, v0.w);
            q.z = packbf2(v1.x, v1.y);
            q.w = packbf2(v1.z, v1.w);
        }
        const int64_t off = (((int64_t)(b * KT_MAX + (j >> 7)) * 12 + (d >> 6)) * 128
                             + (j & 127)) * 128
                          + (((d & 63) * 2) ^ ((j & 7) << 4));
        *reinterpret_cast<uint4*>(mb + off) = q;
    }
}

// ---------------------------------------------------------------------------
// Persistent fused GEMM kernel. NWORKERS resident CTAs pull tiles from
// g_ctr[0] (gemm1: 768 tiles, kt inner / (b,qt) group outer) then g_ctr[1]
// (gemm2: 768 tiles, dt inner, same group order). Phase-2 consumers spin on
// g_done[group] == KT_MAX — deadlock-free because producers are resident
// peers pulling from the same counter (no dependence on CTA dispatch order).
// Per-tile 3-stage TMA pipeline with full/empty mbarriers, re-initialized
// between tiles (all phases drained). 96KB smem, 2 CTAs/SM.
// ---------------------------------------------------------------------------
static constexpr int STG = 32768;
static constexpr int G_SMEM = 3 * STG;   // 98304

__global__ void __launch_bounds__(256, 2)
fused_gemm_kernel(float* __restrict__ out)
{
    extern __shared__ char smem[];
    __shared__ __align__(8) uint64_t mbar_s[6];   // full[0..2], empty[3..5]
    __shared__ float sden[128];
    __shared__ unsigned s_tile;
    const uint32_t sbase = smem_u32(smem);

    const int tid  = threadIdx.x;
    const int warp = tid >> 5;
    const int lane = tid & 31;
    const int wr = warp >> 2, wc = warp & 3;

    const int g    = lane >> 2;
    const int t4   = lane & 3;
    const int lrow = lane & 15;
    const int lgrp = lane >> 4;

    // ===================== Phase 1: gemm1 tiles =====================
    for (;;) {
        __syncthreads();
        if (tid == 0) s_tile = atomicAdd(&g_ctr[0], 1u);
        __syncthreads();
        const unsigned t = s_tile;
        if (t >= (unsigned)G1T) break;

        const int group = (int)t / KT_MAX;
        const int kt = (int)t - group * KT_MAX;
        const int qt = group & 7;
        const int b  = group >> 3;
        const int cnt = g_cnt[b];
        if (kt * 128 >= cnt) {
            if (tid == 0) atomicAdd(&g_done[group], 1u);
            continue;
        }

        if (tid == 0) {
            #pragma unroll
            for (int s = 0; s < 3; ++s) {
                mbar_init(smem_u32(&mbar_s[s]), 1);
                mbar_init(smem_u32(&mbar_s[3 + s]), 8);
            }
            asm volatile("fence.proxy.async.shared::cta;" ::: "memory");
        }
        __syncthreads();

        const int bsel = (lane >> 3) & 1;
        const int brow0 = 32 * wc + (lane & 7) + ((lane >> 4) << 3);

        const char* Asrc = reinterpret_cast<const char*>(g_Qb)
                         + (int64_t)((b * 8 + qt) * 12) * PNL;
        const char* Bsrc = reinterpret_cast<const char*>(g_Mb)
                         + (int64_t)((b * KT_MAX + kt) * 12) * PNL;

        if (tid == 0) {
            #pragma unroll
            for (int s = 0; s < 3; ++s) {
                const uint32_t mb = smem_u32(&mbar_s[s]);
                mbar_expect_tx(mb, STG);
                bulk_g2s(sbase + s * STG,       Asrc + (int64_t)s * PNL, PNL, mb);
                bulk_g2s(sbase + s * STG + PNL, Bsrc + (int64_t)s * PNL, PNL, mb);
            }
        }

        float acc[4][4][4];
        #pragma unroll
        for (int i = 0; i < 4; ++i)
            #pragma unroll
            for (int j = 0; j < 4; ++j)
                #pragma unroll
                for (int k = 0; k < 4; ++k) acc[i][j][k] = 0.f;

        int s = 0, par = 0;
        for (int p = 0; p < 12; ++p) {
            mbar_wait(smem_u32(&mbar_s[s]), par);
            const uint32_t uA = sbase + s * STG;
            const uint32_t uB = uA + PNL;

            #pragma unroll
            for (int kk = 0; kk < 64; kk += 16) {
                uint32_t bb[2][4];
                #pragma unroll
                for (int j = 0; j < 2; ++j) {
                    const int row = brow0 + 16 * j;
                    const uint32_t addr = uB + row * 128 +
                        ((kk * 2 + bsel * 16) ^ ((row & 7) << 4));
                    asm volatile("ldmatrix.sync.aligned.m8n8.x4.shared.b16 {%0,%1,%2,%3}, [%4];"
                                 : "=r"(bb[j][0]), "=r"(bb[j][1]), "=r"(bb[j][2]), "=r"(bb[j][3])
                                 : "r"(addr));
                }
                #pragma unroll
                for (int rt = 0; rt < 4; ++rt) {
                    const int row = 64 * wr + 16 * rt + lrow;
                    const uint32_t addr = uA + row * 128 +
                        ((kk * 2 + lgrp * 16) ^ ((row & 7) << 4));
                    uint32_t a0, a1, a2, a3;
                    asm volatile("ldmatrix.sync.aligned.m8n8.x4.shared.b16 {%0,%1,%2,%3}, [%4];"
                                 : "=r"(a0), "=r"(a1), "=r"(a2), "=r"(a3) : "r"(addr));
                    #pragma unroll
                    for (int nt = 0; nt < 4; ++nt) {
                        const uint32_t v0 = bb[nt >> 1][2 * (nt & 1)];
                        const uint32_t v1 = bb[nt >> 1][2 * (nt & 1) + 1];
                        asm volatile("mma.sync.aligned.m16n8k16.row.col.f32.bf16.bf16.f32 "
                                     "{%0,%1,%2,%3}, {%4,%5,%6,%7}, {%8,%9}, {%0,%1,%2,%3};"
                                     : "+f"(acc[rt][nt][0]), "+f"(acc[rt][nt][1]),
                                       "+f"(acc[rt][nt][2]), "+f"(acc[rt][nt][3])
                                     : "r"(a0), "r"(a1), "r"(a2), "r"(a3), "r"(v0), "r"(v1));
                    }
                }
            }
            if (lane == 0) mbar_arrive(smem_u32(&mbar_s[3 + s]));
            if (tid == 0 && p + 3 < 12) {
                mbar_wait(smem_u32(&mbar_s[3 + s]), par);
                const uint32_t mb = smem_u32(&mbar_s[s]);
                mbar_expect_tx(mb, STG);
                bulk_g2s(sbase + s * STG,       Asrc + (int64_t)(p + 3) * PNL, PNL, mb);
                bulk_g2s(sbase + s * STG + PNL, Bsrc + (int64_t)(p + 3) * PNL, PNL, mb);
            }
            if (++s == 3) { s = 0; par ^= 1; }
        }

        // Epilogue: exp (pad cols -> 0), write P, accumulate denominators.
        char* Pbase = reinterpret_cast<char*>(g_P)
                    + (int64_t)((b * 8 + qt) * 12 + kt * 2) * PNL;
        #pragma unroll
        for (int rt = 0; rt < 4; ++rt) {
            const int r0 = 64 * wr + 16 * rt + g;
            const int r1 = r0 + 8;
            float s0 = 0.f, s1 = 0.f;
            #pragma unroll
            for (int nt = 0; nt < 4; ++nt) {
                const int cl = 32 * wc + 8 * nt + 2 * t4;
                const int ck = kt * 128 + cl;
                const float mk0 = (ck     < cnt) ? 1.f : 0.f;
                const float mk1 = (ck + 1 < cnt) ? 1.f : 0.f;
                const float e0 = mk0 * __expf(acc[rt][nt][0]);
                const float e1 = mk1 * __expf(acc[rt][nt][1]);
                const float e2 = mk0 * __expf(acc[rt][nt][2]);
                const float e3 = mk1 * __expf(acc[rt][nt][3]);
                s0 += e0 + e1;
                s1 += e2 + e3;
                char* pp = Pbase + (int64_t)(cl >> 6) * PNL;
                const int c2 = (cl & 63) * 2;
                *reinterpret_cast<uint32_t*>(pp + r0 * 128 + (c2 ^ ((r0 & 7) << 4))) = packbf2(e0, e1);
                *reinterpret_cast<uint32_t*>(pp + r1 * 128 + (c2 ^ ((r1 & 7) << 4))) = packbf2(e2, e3);
            }
            s0 += __shfl_xor_sync(0xffffffff, s0, 1);
            s0 += __shfl_xor_sync(0xffffffff, s0, 2);
            s1 += __shfl_xor_sync(0xffffffff, s1, 1);
            s1 += __shfl_xor_sync(0xffffffff, s1, 2);
            if (t4 == 0) {
                atomicAdd(&g_den[b * NN + qt * 128 + r0], s0);
                atomicAdd(&g_den[b * NN + qt * 128 + r1], s1);
            }
        }
        __threadfence();
        __syncthreads();
        if (tid == 0) atomicAdd(&g_done[group], 1u);
    }

    // ===================== Phase 2: gemm2 tiles =====================
    const int trow = (lane & 7) + ((lane >> 3) & 1) * 8;
    const int td8  = (lane >> 4) * 8;

    for (;;) {
        __syncthreads();
        if (tid == 0) s_tile = atomicAdd(&g_ctr[1], 1u);
        __syncthreads();
        const unsigned t = s_tile;
        if (t >= (unsigned)G1T) break;

        const int group = (int)t / 6;
        const int dt = (int)t - group * 6;
        const int qt = group & 7;
        const int b  = group >> 3;

        if (tid == 0) {
            #pragma unroll
            for (int s = 0; s < 3; ++s) {
                mbar_init(smem_u32(&mbar_s[s]), 1);
                mbar_init(smem_u32(&mbar_s[3 + s]), 8);
            }
            asm volatile("fence.proxy.async.shared::cta;" ::: "memory");
            while (atomicAdd(&g_done[group], 0u) < (unsigned)KT_MAX)
                __nanosleep(100);
            __threadfence();
        }
        __syncthreads();

        const int cnt = g_cnt[b];
        const int npan = 2 * ((cnt + 127) >> 7);
        if (tid < 128) sden[tid] = g_den[b * NN + qt * 128 + tid];
        __syncthreads();

        const char* Asrc = reinterpret_cast<const char*>(g_P)
                         + (int64_t)((b * 8 + qt) * 12) * PNL;
        const char* Mbase = reinterpret_cast<const char*>(g_Mb);

        auto issue = [&](int p, int s) {
            const uint32_t mb = smem_u32(&mbar_s[s]);
            mbar_expect_tx(mb, STG);
            bulk_g2s(sbase + s * STG, Asrc + (int64_t)p * PNL, PNL, mb);
            const char* B0 = Mbase
                + (int64_t)((b * KT_MAX + (p >> 1)) * 12 + 2 * dt) * PNL
                + (p & 1) * 8192;
            bulk_g2s(sbase + s * STG + PNL,        B0,       8192, mb);
            bulk_g2s(sbase + s * STG + PNL + 8192, B0 + PNL, 8192, mb);
        };

        if (tid == 0) {
            #pragma unroll
            for (int s = 0; s < 3; ++s) if (s < npan) issue(s, s);
        }

        float acc[4][4][4];
        #pragma unroll
        for (int i = 0; i < 4; ++i)
            #pragma unroll
            for (int j = 0; j < 4; ++j)
                #pragma unroll
                for (int k = 0; k < 4; ++k) acc[i][j][k] = 0.f;

        int s = 0, par = 0;
        for (int p = 0; p < npan; ++p) {
            mbar_wait(smem_u32(&mbar_s[s]), par);
            const uint32_t uA = sbase + s * STG;
            const uint32_t uB = uA + PNL;

            #pragma unroll
            for (int kk = 0; kk < 64; kk += 16) {
                uint32_t bb[4][2];
                #pragma unroll
                for (int pair = 0; pair < 2; ++pair) {
                    const int dcol = 32 * wc + pair * 16 + td8;
                    const int row  = kk + trow;
                    const uint32_t addr = uB + (dcol >> 6) * 8192 + row * 128 +
                        (((dcol & 63) * 2) ^ ((row & 7) << 4));
                    asm volatile("ldmatrix.sync.aligned.m8n8.x4.trans.shared.b16 {%0,%1,%2,%3}, [%4];"
                                 : "=r"(bb[2 * pair][0]), "=r"(bb[2 * pair][1]),
                                   "=r"(bb[2 * pair + 1][0]), "=r"(bb[2 * pair + 1][1])
                                 : "r"(addr));
                }
                #pragma unroll
                for (int rt = 0; rt < 4; ++rt) {
                    const int row = 64 * wr + 16 * rt + lrow;
                    const uint32_t addr = uA + row * 128 +
                        ((kk * 2 + lgrp * 16) ^ ((row & 7) << 4));
                    uint32_t a0, a1, a2, a3;
                    asm volatile("ldmatrix.sync.aligned.m8n8.x4.shared.b16 {%0,%1,%2,%3}, [%4];"
                                 : "=r"(a0), "=r"(a1), "=r"(a2), "=r"(a3) : "r"(addr));
                    #pragma unroll
                    for (int nt = 0; nt < 4; ++nt) {
                        asm volatile("mma.sync.aligned.m16n8k16.row.col.f32.bf16.bf16.f32 "
                                     "{%0,%1,%2,%3}, {%4,%5,%6,%7}, {%8,%9}, {%0,%1,%2,%3};"
                                     : "+f"(acc[rt][nt][0]), "+f"(acc[rt][nt][1]),
                                       "+f"(acc[rt][nt][2]), "+f"(acc[rt][nt][3])
                                     : "r"(a0), "r"(a1), "r"(a2), "r"(a3),
                                       "r"(bb[nt][0]), "r"(bb[nt][1]));
                    }
                }
            }
            if (lane == 0) mbar_arrive(smem_u32(&mbar_s[3 + s]));
            if (tid == 0 && p + 3 < npan) {
                mbar_wait(smem_u32(&mbar_s[3 + s]), par);
                issue(p + 3, s);
            }
            if (++s == 3) { s = 0; par ^= 1; }
        }

        // Epilogue: divide by denom, store to out[..., 768 + dt*128 + ...]
        #pragma unroll
        for (int rt = 0; rt < 4; ++rt) {
            const int r0 = 64 * wr + 16 * rt + g;
            const int r1 = r0 + 8;
            const float inv0 = 1.f / sden[r0];
            const float inv1 = 1.f / sden[r1];
            float* o0 = out + (int64_t)(b * NN + qt * 128 + r0) * D2 + DD + dt * 128;
            float* o1 = out + (int64_t)(b * NN + qt * 128 + r1) * D2 + DD + dt * 128;
            #pragma unroll
            for (int nt = 0; nt < 4; ++nt) {
                const int cl = 32 * wc + 8 * nt + 2 * t4;
                *reinterpret_cast<float2*>(o0 + cl) =
                    make_float2(acc[rt][nt][0] * inv0, acc[rt][nt][1] * inv0);
                *reinterpret_cast<float2*>(o1 + cl) =
                    make_float2(acc[rt][nt][2] * inv1, acc[rt][nt][3] * inv1);
            }
        }
    }
}

// ---------------------------------------------------------------------------
extern "C" void kernel_launch(void* const* d_in, const int* in_sizes, int n_in,
                              void* d_out, int out_size)
{
    const float* input     = (const float*)d_in[0];
    const float* memory    = (const float*)d_in[1];
    const int*   mask      = (const int*)d_in[2];
    // d_in[3] = w_in : provably unused (softmax shift-invariance)
    const float* dot_scale = (const float*)d_in[4];
    float* out = (float*)d_out;

    compact_kernel<<<BB, 1024>>>(mask);
    prep_kernel<<<1024, 256>>>(input, memory, dot_scale, out);

    cudaFuncSetAttribute(fused_gemm_kernel,
                         cudaFuncAttributeMaxDynamicSharedMemorySize, G_SMEM);
    fused_gemm_kernel<<<NWORKERS, 256, G_SMEM>>>(out);
}

// round 13
// speedup vs baseline: 1.0162x; 1.0162x over previous
#include <cuda_runtime.h>
#include <cuda_bf16.h>
#include <cstdint>

// Problem constants
static constexpr int BB = 16;
static constexpr int NN = 1024;
static constexpr int MM = 1024;
static constexpr int DD = 768;
static constexpr int D2 = 2 * DD;

static constexpr int PNL = 16384;     // one panel: 128 rows x 128 bytes
static constexpr int KT_MAX = 6;      // max compacted key tiles
static constexpr int CKEYS = KT_MAX * 128;   // 768 compacted key slots

// Staging buffers (device globals; allocation is forbidden)
// g_Qb : [b][qtile 8][panel 12][128 q rows][128B]   (Q*dot_scale, bf16, SW128)
// g_Mb : [b][ktile 6][dpanel 12][128 k rows][128B]  (compacted memory, K-major)
// g_P  : [b][qtile 8][kpanel 12][128 q rows][128B]  (exp weights, bf16)
__device__ __align__(16) __nv_bfloat16 g_Qb [(size_t)BB * NN * DD];
__device__ __align__(16) __nv_bfloat16 g_Mb [(size_t)BB * CKEYS * DD];
__device__ __align__(16) __nv_bfloat16 g_P  [(size_t)BB * NN * CKEYS];
__device__ float g_den[BB * NN];
__device__ int   g_idx[BB * CKEYS];
__device__ int   g_cnt[BB];

__device__ __forceinline__ uint32_t smem_u32(const void* p) {
    return (uint32_t)__cvta_generic_to_shared(p);
}
__device__ __forceinline__ uint32_t packbf2(float lo, float hi) {
    uint32_t r;
    asm("cvt.rn.bf16x2.f32 %0, %1, %2;" : "=r"(r) : "f"(hi), "f"(lo));
    return r;
}
__device__ __forceinline__ void mbar_init(uint32_t mb, uint32_t cnt) {
    asm volatile("mbarrier.init.shared.b64 [%0], %1;" :: "r"(mb), "r"(cnt) : "memory");
}
__device__ __forceinline__ void mbar_arrive(uint32_t mb) {
    asm volatile("mbarrier.arrive.shared.b64 _, [%0];" :: "r"(mb) : "memory");
}
__device__ __forceinline__ void mbar_expect_tx(uint32_t mb, uint32_t bytes) {
    asm volatile("mbarrier.arrive.expect_tx.shared.b64 _, [%0], %1;"
                 :: "r"(mb), "r"(bytes) : "memory");
}
__device__ __forceinline__ void bulk_g2s(uint32_t dst, const void* src,
                                         uint32_t bytes, uint32_t mb) {
    asm volatile("cp.async.bulk.shared::cta.global.mbarrier::complete_tx::bytes "
                 "[%0], [%1], %2, [%3];"
                 :: "r"(dst), "l"(src), "r"(bytes), "r"(mb) : "memory");
}
__device__ __forceinline__ void mbar_wait(uint32_t mb, uint32_t parity) {
    asm volatile(
        "{\n\t"
        ".reg .pred P1;\n\t"
        "LAB_WAIT_%=:\n\t"
        "mbarrier.try_wait.parity.acquire.cta.shared::cta.b64 P1, [%0], %1, 0x989680;\n\t"
        "@P1 bra LAB_DONE_%=;\n\t"
        "bra LAB_WAIT_%=;\n\t"
        "LAB_DONE_%=:\n\t"
        "}" :: "r"(mb), "r"(parity) : "memory");
}

// ---------------------------------------------------------------------------
// Compaction: per batch, gather indices of unmasked keys (warp-scan prefix).
// ---------------------------------------------------------------------------
__global__ void compact_kernel(const int* __restrict__ mask)
{
    const int b   = blockIdx.x;
    const int tid = threadIdx.x;   // 1024 threads
    __shared__ int wbase[33];

    const int v = (mask[b * MM + tid] != 0) ? 1 : 0;
    const uint32_t bal = __ballot_sync(0xffffffffu, v);
    const int lane = tid & 31, w = tid >> 5;
    if (lane == 0) wbase[w + 1] = __popc(bal);
    __syncthreads();
    if (tid < 32) {
        int x = wbase[tid + 1];
        #pragma unroll
        for (int d = 1; d < 32; d <<= 1) {
            int n = __shfl_up_sync(0xffffffffu, x, d);
            if (tid >= d) x += n;
        }
        wbase[tid + 1] = x;
        if (tid == 0) wbase[0] = 0;
    }
    __syncthreads();
    const int cnt = wbase[32];
    if (v) {
        const int pos = wbase[w] + __popc(bal & ((1u << lane) - 1u));
        if (pos < CKEYS) g_idx[b * CKEYS + pos] = tid;
    }
    if (tid < CKEYS - cnt) g_idx[b * CKEYS + cnt + tid] = -1;
    if (tid == 0) g_cnt[b] = (cnt < CKEYS) ? cnt : CKEYS;
}

// ---------------------------------------------------------------------------
// Prep: Qb staging, compacted Mb staging (pad rows zero), zero g_den.
// (out[:, :768] copy moved into gemm2's prologue.)
// ---------------------------------------------------------------------------
__global__ void prep_kernel(const float* __restrict__ input,
                            const float* __restrict__ memory,
                            const float* __restrict__ dot_scale)
{
    const int64_t stride = (int64_t)gridDim.x * blockDim.x;
    const int64_t gtid   = (int64_t)blockIdx.x * blockDim.x + threadIdx.x;
    char* qb = reinterpret_cast<char*>(g_Qb);
    char* mb = reinterpret_cast<char*>(g_Mb);

    if (gtid < BB * NN) g_den[gtid] = 0.f;

    const int64_t total_q = (int64_t)BB * NN * DD / 8;
    for (int64_t i = gtid; i < total_q; i += stride) {
        const int64_t e = i * 8;
        const int d = (int)(e % DD);
        const int64_t row = e / DD;          // b*NN + n
        const int b = (int)(row >> 10);
        const int n = (int)(row & 1023);
        float4 v0 = *reinterpret_cast<const float4*>(input + e);
        float4 v1 = *reinterpret_cast<const float4*>(input + e + 4);
        float4 s0 = *reinterpret_cast<const float4*>(dot_scale + d);
        float4 s1 = *reinterpret_cast<const float4*>(dot_scale + d + 4);
        uint4 q;
        q.x = packbf2(v0.x * s0.x, v0.y * s0.y);
        q.y = packbf2(v0.z * s0.z, v0.w * s0.w);
        q.z = packbf2(v1.x * s1.x, v1.y * s1.y);
        q.w = packbf2(v1.z * s1.z, v1.w * s1.w);
        const int64_t off = (((int64_t)(b * 8 + (n >> 7)) * 12 + (d >> 6)) * 128
                             + (n & 127)) * 128
                          + (((d & 63) * 2) ^ ((n & 7) << 4));
        *reinterpret_cast<uint4*>(qb + off) = q;
    }

    const int64_t total_m = (int64_t)BB * CKEYS * DD / 8;
    for (int64_t i = gtid; i < total_m; i += stride) {
        const int64_t e = i * 8;
        const int d = (int)(e % DD);
        const int64_t row = e / DD;          // b*CKEYS + j
        const int b = (int)(row / CKEYS);
        const int j = (int)(row - (int64_t)b * CKEYS);
        const int src = g_idx[b * CKEYS + j];
        uint4 q = make_uint4(0u, 0u, 0u, 0u);
        if (src >= 0) {
            const float* mrow = memory + ((int64_t)(b * MM + src)) * DD + d;
            float4 v0 = *reinterpret_cast<const float4*>(mrow);
            float4 v1 = *reinterpret_cast<const float4*>(mrow + 4);
            q.x = packbf2(v0.x, v0.y);
            q.y = packbf2(v0.z, v0.w);
            q.z = packbf2(v1.x, v1.y);
            q.w = packbf2(v1.z, v1.w);
        }
        const int64_t off = (((int64_t)(b * KT_MAX + (j >> 7)) * 12 + (d >> 6)) * 128
                             + (j & 127)) * 128
                          + (((d & 63) * 2) ^ ((j & 7) << 4));
        *reinterpret_cast<uint4*>(mb + off) = q;
    }
}

// ---------------------------------------------------------------------------
// GEMM cores: CTA tile 128x128, 8 warps (2x4), warp 64x32.
// 3-stage TMA pipeline with full/empty mbarriers. 96KB smem, 2 CTAs/SM.
// ---------------------------------------------------------------------------
static constexpr int STG = 32768;
static constexpr int G_SMEM = 3 * STG;   // 98304

// GEMM1 + exp: S = Q@Mc^T; P = exp(S) (pad cols -> 0); denom += rowsum.
__global__ void __launch_bounds__(256, 2)
gemm1_kernel()
{
    const int qt = blockIdx.x, kt = blockIdx.y, b = blockIdx.z;
    const int cnt = g_cnt[b];
    if (kt * 128 >= cnt) return;

    extern __shared__ char smem[];
    __shared__ __align__(8) uint64_t mbar_s[6];   // full[0..2], empty[3..5]
    const uint32_t sbase = smem_u32(smem);

    const int tid  = threadIdx.x;
    const int warp = tid >> 5;
    const int lane = tid & 31;
    const int wr = warp >> 2, wc = warp & 3;

    const int g    = lane >> 2;
    const int t4   = lane & 3;
    const int lrow = lane & 15;
    const int lgrp = lane >> 4;
    const int bsel = (lane >> 3) & 1;
    const int brow0 = 32 * wc + (lane & 7) + ((lane >> 4) << 3);

    if (tid == 0) {
        #pragma unroll
        for (int s = 0; s < 3; ++s) {
            mbar_init(smem_u32(&mbar_s[s]), 1);
            mbar_init(smem_u32(&mbar_s[3 + s]), 8);
        }
        asm volatile("fence.proxy.async.shared::cta;" ::: "memory");
    }
    __syncthreads();

    const char* Asrc = reinterpret_cast<const char*>(g_Qb)
                     + (int64_t)((b * 8 + qt) * 12) * PNL;
    const char* Bsrc = reinterpret_cast<const char*>(g_Mb)
                     + (int64_t)((b * KT_MAX + kt) * 12) * PNL;

    if (tid == 0) {
        #pragma unroll
        for (int s = 0; s < 3; ++s) {
            const uint32_t mb = smem_u32(&mbar_s[s]);
            mbar_expect_tx(mb, STG);
            bulk_g2s(sbase + s * STG,       Asrc + (int64_t)s * PNL, PNL, mb);
            bulk_g2s(sbase + s * STG + PNL, Bsrc + (int64_t)s * PNL, PNL, mb);
        }
    }

    float acc[4][4][4];
    #pragma unroll
    for (int i = 0; i < 4; ++i)
        #pragma unroll
        for (int j = 0; j < 4; ++j)
            #pragma unroll
            for (int k = 0; k < 4; ++k) acc[i][j][k] = 0.f;

    int s = 0, par = 0;
    for (int p = 0; p < 12; ++p) {
        mbar_wait(smem_u32(&mbar_s[s]), par);
        const uint32_t uA = sbase + s * STG;
        const uint32_t uB = uA + PNL;

        #pragma unroll
        for (int kk = 0; kk < 64; kk += 16) {
            uint32_t bb[2][4];
            #pragma unroll
            for (int j = 0; j < 2; ++j) {
                const int row = brow0 + 16 * j;
                const uint32_t addr = uB + row * 128 +
                    ((kk * 2 + bsel * 16) ^ ((row & 7) << 4));
                asm volatile("ldmatrix.sync.aligned.m8n8.x4.shared.b16 {%0,%1,%2,%3}, [%4];"
                             : "=r"(bb[j][0]), "=r"(bb[j][1]), "=r"(bb[j][2]), "=r"(bb[j][3])
                             : "r"(addr));
            }
            #pragma unroll
            for (int rt = 0; rt < 4; ++rt) {
                const int row = 64 * wr + 16 * rt + lrow;
                const uint32_t addr = uA + row * 128 +
                    ((kk * 2 + lgrp * 16) ^ ((row & 7) << 4));
                uint32_t a0, a1, a2, a3;
                asm volatile("ldmatrix.sync.aligned.m8n8.x4.shared.b16 {%0,%1,%2,%3}, [%4];"
                             : "=r"(a0), "=r"(a1), "=r"(a2), "=r"(a3) : "r"(addr));
                #pragma unroll
                for (int nt = 0; nt < 4; ++nt) {
                    const uint32_t v0 = bb[nt >> 1][2 * (nt & 1)];
                    const uint32_t v1 = bb[nt >> 1][2 * (nt & 1) + 1];
                    asm volatile("mma.sync.aligned.m16n8k16.row.col.f32.bf16.bf16.f32 "
                                 "{%0,%1,%2,%3}, {%4,%5,%6,%7}, {%8,%9}, {%0,%1,%2,%3};"
                                 : "+f"(acc[rt][nt][0]), "+f"(acc[rt][nt][1]),
                                   "+f"(acc[rt][nt][2]), "+f"(acc[rt][nt][3])
                                 : "r"(a0), "r"(a1), "r"(a2), "r"(a3), "r"(v0), "r"(v1));
                }
            }
        }
        if (lane == 0) mbar_arrive(smem_u32(&mbar_s[3 + s]));
        if (tid == 0 && p + 3 < 12) {
            mbar_wait(smem_u32(&mbar_s[3 + s]), par);
            const uint32_t mb = smem_u32(&mbar_s[s]);
            mbar_expect_tx(mb, STG);
            bulk_g2s(sbase + s * STG,       Asrc + (int64_t)(p + 3) * PNL, PNL, mb);
            bulk_g2s(sbase + s * STG + PNL, Bsrc + (int64_t)(p + 3) * PNL, PNL, mb);
        }
        if (++s == 3) { s = 0; par ^= 1; }
    }

    // Epilogue: exp (pad cols -> 0), write P panels, accumulate denominators.
    char* Pbase = reinterpret_cast<char*>(g_P)
                + (int64_t)((b * 8 + qt) * 12 + kt * 2) * PNL;
    #pragma unroll
    for (int rt = 0; rt < 4; ++rt) {
        const int r0 = 64 * wr + 16 * rt + g;
        const int r1 = r0 + 8;
        float s0 = 0.f, s1 = 0.f;
        #pragma unroll
        for (int nt = 0; nt < 4; ++nt) {
            const int cl = 32 * wc + 8 * nt + 2 * t4;
            const int ck = kt * 128 + cl;
            const float mk0 = (ck     < cnt) ? 1.f : 0.f;
            const float mk1 = (ck + 1 < cnt) ? 1.f : 0.f;
            const float e0 = mk0 * __expf(acc[rt][nt][0]);
            const float e1 = mk1 * __expf(acc[rt][nt][1]);
            const float e2 = mk0 * __expf(acc[rt][nt][2]);
            const float e3 = mk1 * __expf(acc[rt][nt][3]);
            s0 += e0 + e1;
            s1 += e2 + e3;
            char* pp = Pbase + (int64_t)(cl >> 6) * PNL;
            const int c2 = (cl & 63) * 2;
            *reinterpret_cast<uint32_t*>(pp + r0 * 128 + (c2 ^ ((r0 & 7) << 4))) = packbf2(e0, e1);
            *reinterpret_cast<uint32_t*>(pp + r1 * 128 + (c2 ^ ((r1 & 7) << 4))) = packbf2(e2, e3);
        }
        s0 += __shfl_xor_sync(0xffffffff, s0, 1);
        s0 += __shfl_xor_sync(0xffffffff, s0, 2);
        s1 += __shfl_xor_sync(0xffffffff, s1, 1);
        s1 += __shfl_xor_sync(0xffffffff, s1, 2);
        if (t4 == 0) {
            atomicAdd(&g_den[b * NN + qt * 128 + r0], s0);
            atomicAdd(&g_den[b * NN + qt * 128 + r1], s1);
        }
    }
}

// GEMM2 + normalize: O = P @ Mc / denom -> out[..., 768:].
// Also copies its [128 x 128] input block into out[..., :768] (dt covers all
// 6 column tiles), overlapped with the TMA/compute pipeline.
__global__ void __launch_bounds__(256, 2)
gemm2_kernel(float* __restrict__ out, const float* __restrict__ input)
{
    const int qt = blockIdx.x, dt = blockIdx.y, b = blockIdx.z;
    const int cnt = g_cnt[b];
    const int npan = 2 * ((cnt + 127) >> 7);

    extern __shared__ char smem[];
    __shared__ __align__(8) uint64_t mbar_s[6];   // full[0..2], empty[3..5]
    __shared__ float sden[128];
    const uint32_t sbase = smem_u32(smem);

    const int tid  = threadIdx.x;
    const int warp = tid >> 5;
    const int lane = tid & 31;
    const int wr = warp >> 2, wc = warp & 3;

    const int g    = lane >> 2;
    const int t4   = lane & 3;
    const int lrow = lane & 15;
    const int lgrp = lane >> 4;

    const int trow = (lane & 7) + ((lane >> 3) & 1) * 8;
    const int td8  = (lane >> 4) * 8;

    if (tid == 0) {
        #pragma unroll
        for (int s = 0; s < 3; ++s) {
            mbar_init(smem_u32(&mbar_s[s]), 1);
            mbar_init(smem_u32(&mbar_s[3 + s]), 8);
        }
        asm volatile("fence.proxy.async.shared::cta;" ::: "memory");
    }
    if (tid < 128) sden[tid] = g_den[b * NN + qt * 128 + tid];
    __syncthreads();

    const char* Asrc = reinterpret_cast<const char*>(g_P)
                     + (int64_t)((b * 8 + qt) * 12) * PNL;
    const char* Mbase = reinterpret_cast<const char*>(g_Mb);

    auto issue = [&](int p, int s) {
        const uint32_t mb = smem_u32(&mbar_s[s]);
        mbar_expect_tx(mb, STG);
        bulk_g2s(sbase + s * STG, Asrc + (int64_t)p * PNL, PNL, mb);
        const char* B0 = Mbase
            + (int64_t)((b * KT_MAX + (p >> 1)) * 12 + 2 * dt) * PNL
            + (p & 1) * 8192;
        bulk_g2s(sbase + s * STG + PNL,        B0,       8192, mb);
        bulk_g2s(sbase + s * STG + PNL + 8192, B0 + PNL, 8192, mb);
    };

    if (tid == 0) {
        #pragma unroll
        for (int s = 0; s < 3; ++s) if (s < npan) issue(s, s);
    }

    // Overlapped copy: out[b, qt*128 + r, dt*128 + c] = input[...], fp32.
    // 128 rows x 32 float4 = 4096 vec-iters, 16 per thread; LDG/STG stream
    // rides under the TMA waits + tensor mainloop.
    {
        const float* isrc = input + (int64_t)(b * NN + qt * 128) * DD + dt * 128;
        float* odst = out + (int64_t)(b * NN + qt * 128) * D2 + dt * 128;
        #pragma unroll 4
        for (int i = tid; i < 128 * 32; i += 256) {
            const int r  = i >> 5;
            const int c4 = (i & 31) * 4;
            float4 v = *reinterpret_cast<const float4*>(isrc + (int64_t)r * DD + c4);
            *reinterpret_cast<float4*>(odst + (int64_t)r * D2 + c4) = v;
        }
    }

    float acc[4][4][4];
    #pragma unroll
    for (int i = 0; i < 4; ++i)
        #pragma unroll
        for (int j = 0; j < 4; ++j)
            #pragma unroll
            for (int k = 0; k < 4; ++k) acc[i][j][k] = 0.f;

    int s = 0, par = 0;
    for (int p = 0; p < npan; ++p) {
        mbar_wait(smem_u32(&mbar_s[s]), par);
        const uint32_t uA = sbase + s * STG;
        const uint32_t uB = uA + PNL;

        #pragma unroll
        for (int kk = 0; kk < 64; kk += 16) {
            uint32_t bb[4][2];
            #pragma unroll
            for (int pair = 0; pair < 2; ++pair) {
                const int dcol = 32 * wc + pair * 16 + td8;
                const int row  = kk + trow;
                const uint32_t addr = uB + (dcol >> 6) * 8192 + row * 128 +
                    (((dcol & 63) * 2) ^ ((row & 7) << 4));
                asm volatile("ldmatrix.sync.aligned.m8n8.x4.trans.shared.b16 {%0,%1,%2,%3}, [%4];"
                             : "=r"(bb[2 * pair][0]), "=r"(bb[2 * pair][1]),
                               "=r"(bb[2 * pair + 1][0]), "=r"(bb[2 * pair + 1][1])
                             : "r"(addr));
            }
            #pragma unroll
            for (int rt = 0; rt < 4; ++rt) {
                const int row = 64 * wr + 16 * rt + lrow;
                const uint32_t addr = uA + row * 128 +
                    ((kk * 2 + lgrp * 16) ^ ((row & 7) << 4));
                uint32_t a0, a1, a2, a3;
                asm volatile("ldmatrix.sync.aligned.m8n8.x4.shared.b16 {%0,%1,%2,%3}, [%4];"
                             : "=r"(a0), "=r"(a1), "=r"(a2), "=r"(a3) : "r"(addr));
                #pragma unroll
                for (int nt = 0; nt < 4; ++nt) {
                    asm volatile("mma.sync.aligned.m16n8k16.row.col.f32.bf16.bf16.f32 "
                                 "{%0,%1,%2,%3}, {%4,%5,%6,%7}, {%8,%9}, {%0,%1,%2,%3};"
                                 : "+f"(acc[rt][nt][0]), "+f"(acc[rt][nt][1]),
                                   "+f"(acc[rt][nt][2]), "+f"(acc[rt][nt][3])
                                 : "r"(a0), "r"(a1), "r"(a2), "r"(a3),
                                   "r"(bb[nt][0]), "r"(bb[nt][1]));
                }
            }
        }
        if (lane == 0) mbar_arrive(smem_u32(&mbar_s[3 + s]));
        if (tid == 0 && p + 3 < npan) {
            mbar_wait(smem_u32(&mbar_s[3 + s]), par);
            issue(p + 3, s);
        }
        if (++s == 3) { s = 0; par ^= 1; }
    }

    // Epilogue: divide by denom, store to out[..., 768 + dt*128 + ...]
    #pragma unroll
    for (int rt = 0; rt < 4; ++rt) {
        const int r0 = 64 * wr + 16 * rt + g;
        const int r1 = r0 + 8;
        const float inv0 = 1.f / sden[r0];
        const float inv1 = 1.f / sden[r1];
        float* o0 = out + (int64_t)(b * NN + qt * 128 + r0) * D2 + DD + dt * 128;
        float* o1 = out + (int64_t)(b * NN + qt * 128 + r1) * D2 + DD + dt * 128;
        #pragma unroll
        for (int nt = 0; nt < 4; ++nt) {
            const int cl = 32 * wc + 8 * nt + 2 * t4;
            *reinterpret_cast<float2*>(o0 + cl) =
                make_float2(acc[rt][nt][0] * inv0, acc[rt][nt][1] * inv0);
            *reinterpret_cast<float2*>(o1 + cl) =
                make_float2(acc[rt][nt][2] * inv1, acc[rt][nt][3] * inv1);
        }
    }
}

// ---------------------------------------------------------------------------
extern "C" void kernel_launch(void* const* d_in, const int* in_sizes, int n_in,
                              void* d_out, int out_size)
{
    const float* input     = (const float*)d_in[0];
    const float* memory    = (const float*)d_in[1];
    const int*   mask      = (const int*)d_in[2];
    // d_in[3] = w_in : provably unused (softmax shift-invariance)
    const float* dot_scale = (const float*)d_in[4];
    float* out = (float*)d_out;

    compact_kernel<<<BB, 1024>>>(mask);
    prep_kernel<<<1024, 256>>>(input, memory, dot_scale);

    cudaFuncSetAttribute(gemm1_kernel,
                         cudaFuncAttributeMaxDynamicSharedMemorySize, G_SMEM);
    cudaFuncSetAttribute(gemm2_kernel,
                         cudaFuncAttributeMaxDynamicSharedMemorySize, G_SMEM);

    gemm1_kernel<<<dim3(8, KT_MAX, BB), 256, G_SMEM>>>();
    gemm2_kernel<<<dim3(8, 6, BB), 256, G_SMEM>>>(out, input);
}